// round 3
// baseline (speedup 1.0000x reference)
#include <cuda_runtime.h>

#define NP 8192
#define NT 8192
#define CAP 256
#define ROW_F4 (NT/4)

// ---------------- static scratch ----------------
__device__ __align__(16) float d_pa[NP * 64];
__device__ __align__(16) float d_pb[NP * 64];
__device__ __align__(16) float d_ta[NT * 64];
__device__ __align__(16) float d_tb[NT * 64];
__device__ __align__(16) float d_prp[NT * 16];   // proj of t3 for p-side L4 agg
__device__ __align__(16) float d_prt[NP * 16];   // proj of p3 for t-side L4 agg
__device__ float d_lp[NP];                        // dot(p4, w_ac[0:16])
__device__ float d_td[NT];                        // dot(t4, w_ac[16:32])
__device__ float d_logits[NT];
__device__ int d_rcnt[NP];
__device__ int d_ccnt[NT];
__device__ int d_rlist[NP * CAP];
__device__ int d_clist[NT * CAP];
__device__ unsigned g_arrive = 0;
__device__ volatile unsigned g_gen = 0;
__device__ float g_max, g_inv;

// ---------------- grid-wide barrier (all blocks resident) ----------------
__device__ __forceinline__ void gbar(int nb, unsigned& gen) {
    __syncthreads();
    if (threadIdx.x == 0) {
        __threadfence();
        unsigned a = atomicAdd(&g_arrive, 1u);
        if (a == (unsigned)nb - 1u) {
            atomicExch(&g_arrive, 0u);
            __threadfence();
            g_gen = gen + 1u;
        } else {
            while (g_gen == gen) { __nanosleep(64); }
        }
    }
    gen += 1u;
    __syncthreads();
    __threadfence();
}

// ---------------- direct layer: out = relu([self|agg] @ W + B) ----------------
template <int IN, int OUT, bool SELF_FIRST>
__device__ __forceinline__ void layer_node(
    int node, const float* __restrict__ self_f, const float* __restrict__ other_f,
    const int* __restrict__ cnt, const int* __restrict__ list,
    const float* sW, const float* sB, float* __restrict__ out_f,
    float* xs, int lane)
{
    constexpr int C = 2 * IN;
    constexpr int SOFF = SELF_FIRST ? 0 : IN;
    constexpr int AOFF = SELF_FIRST ? IN : 0;
#pragma unroll
    for (int k = lane; k < IN; k += 32) xs[SOFF + k] = self_f[node * IN + k];

    constexpr int V = IN / 4;
    constexpr int G = 32 / V;
    int v = lane % V, g = lane / V;
    float4 acc = make_float4(0.f, 0.f, 0.f, 0.f);
    int n = min(cnt[node], CAP);
    const int* lst = list + node * CAP;
    for (int e = g; e < n; e += G) {
        int nbr = lst[e];
        float4 t4 = *reinterpret_cast<const float4*>(other_f + nbr * IN + v * 4);
        acc.x += t4.x; acc.y += t4.y; acc.z += t4.z; acc.w += t4.w;
    }
#pragma unroll
    for (int d = G / 2; d > 0; d >>= 1) {
        acc.x += __shfl_down_sync(0xffffffffu, acc.x, d * V);
        acc.y += __shfl_down_sync(0xffffffffu, acc.y, d * V);
        acc.z += __shfl_down_sync(0xffffffffu, acc.z, d * V);
        acc.w += __shfl_down_sync(0xffffffffu, acc.w, d * V);
    }
    if (g == 0) *reinterpret_cast<float4*>(xs + AOFF + v * 4) = acc;
    __syncwarp();

    constexpr int JPL = (OUT + 31) / 32;
    if (lane < OUT) {
        float a[JPL];
#pragma unroll
        for (int jj = 0; jj < JPL; jj++) a[jj] = sB[lane + jj * 32];
#pragma unroll
        for (int k = 0; k < C; k++) {
            float xv = xs[k];
#pragma unroll
            for (int jj = 0; jj < JPL; jj++) a[jj] += xv * sW[k * OUT + lane + jj * 32];
        }
#pragma unroll
        for (int jj = 0; jj < JPL; jj++)
            out_f[node * OUT + lane + jj * 32] = fmaxf(a[jj], 0.f);
    }
    __syncwarp();
}

// ---------------- projection: proj[node] = feat[node] @ Wagg  (64 -> 16) ----------------
template <int IN, int OUT>
__device__ __forceinline__ void proj_node(
    int node, const float* __restrict__ feat, const float* sWagg,
    float* __restrict__ proj, float* xs, int lane)
{
#pragma unroll
    for (int k = lane; k < IN; k += 32) xs[k] = feat[node * IN + k];
    __syncwarp();
    if (lane < OUT) {
        float a = 0.f;
#pragma unroll
        for (int k = 0; k < IN; k++) a += xs[k] * sWagg[k * OUT + lane];
        proj[node * OUT + lane] = a;
    }
    __syncwarp();
}

// ---------------- L4 combine: out = relu(self@Wself + sum proj[nbr] + B); dot with w_ac ----------------
template <int IN, int OUT>
__device__ __forceinline__ void l4_node(
    int node, const float* __restrict__ self_f, const float* __restrict__ proj_other,
    const int* __restrict__ cnt, const int* __restrict__ list,
    const float* sWself, const float* sB, const float* sWac,
    float* __restrict__ out_f, float* __restrict__ dotv, float* xs, int lane)
{
#pragma unroll
    for (int k = lane; k < IN; k += 32) xs[k] = self_f[node * IN + k];

    int v = lane & 3, g = lane >> 2;   // V=4 over 16 dims, G=8
    float4 acc = make_float4(0.f, 0.f, 0.f, 0.f);
    int n = min(cnt[node], CAP);
    const int* lst = list + node * CAP;
    for (int e = g; e < n; e += 8) {
        float4 t4 = *reinterpret_cast<const float4*>(proj_other + lst[e] * OUT + v * 4);
        acc.x += t4.x; acc.y += t4.y; acc.z += t4.z; acc.w += t4.w;
    }
#pragma unroll
    for (int d = 4; d > 0; d >>= 1) {
        acc.x += __shfl_down_sync(0xffffffffu, acc.x, d * 4);
        acc.y += __shfl_down_sync(0xffffffffu, acc.y, d * 4);
        acc.z += __shfl_down_sync(0xffffffffu, acc.z, d * 4);
        acc.w += __shfl_down_sync(0xffffffffu, acc.w, d * 4);
    }
    if (g == 0) *reinterpret_cast<float4*>(xs + IN + v * 4) = acc;
    __syncwarp();

    float contrib = 0.f;
    if (lane < OUT) {
        float a = sB[lane] + xs[IN + lane];
#pragma unroll
        for (int k = 0; k < IN; k++) a += xs[k] * sWself[k * OUT + lane];
        float r = fmaxf(a, 0.f);
        out_f[node * OUT + lane] = r;
        contrib = r * sWac[lane];
    }
#pragma unroll
    for (int d = 16; d > 0; d >>= 1)
        contrib += __shfl_down_sync(0xffffffffu, contrib, d);
    if (lane == 0) dotv[node] = contrib;
    __syncwarp();
}

// ---------------- the single persistent kernel ----------------
__global__ void __launch_bounds__(256) fused_k(
    const float* __restrict__ p0, const float* __restrict__ t0, const float* __restrict__ adj,
    const float* __restrict__ wp1, const float* __restrict__ bp1,
    const float* __restrict__ wt1, const float* __restrict__ bt1,
    const float* __restrict__ wp2, const float* __restrict__ bp2,
    const float* __restrict__ wt2, const float* __restrict__ bt2,
    const float* __restrict__ wp3, const float* __restrict__ bp3,
    const float* __restrict__ wt3, const float* __restrict__ bt3,
    const float* __restrict__ wp4, const float* __restrict__ bp4,
    const float* __restrict__ wt4, const float* __restrict__ bt4,
    const float* __restrict__ wac, const float* __restrict__ bac,
    float* __restrict__ out, int nb)
{
    __shared__ float sWp[2048];
    __shared__ float sWt[2048];
    __shared__ float sBp[64];
    __shared__ float sBt[64];
    __shared__ float sAC[32];
    __shared__ __align__(16) float sX[8][128];
    __shared__ int s_list[CAP];
    __shared__ int s_cnt;
    __shared__ float sRed[256];

    int tid = threadIdx.x, warp = tid >> 5, lane = tid & 31;
    unsigned gen = g_gen;
    int tw = nb * 8;
    int gw = blockIdx.x * 8 + warp;

    // ---- P0: zero column counters ----
    for (int i = blockIdx.x * 256 + tid; i < NT; i += nb * 256) d_ccnt[i] = 0;
    gbar(nb, gen);

    // ---- P1: build adjacency lists (one streaming pass over adj) ----
    for (int row = blockIdx.x; row < NP; row += nb) {
        if (tid == 0) s_cnt = 0;
        __syncthreads();
        const float4* a4 = reinterpret_cast<const float4*>(adj) + (size_t)row * ROW_F4;
        for (int c4 = tid; c4 < ROW_F4; c4 += 256) {
            float4 v = __ldcs(&a4[c4]);
            if (v.x != 0.f || v.y != 0.f || v.z != 0.f || v.w != 0.f) {
                int jb = c4 << 2;
                float vals[4] = {v.x, v.y, v.z, v.w};
#pragma unroll
                for (int q = 0; q < 4; q++) {
                    if (vals[q] != 0.f) {
                        int j = jb + q;
                        int slot = atomicAdd(&s_cnt, 1);
                        if (slot < CAP) s_list[slot] = j;
                        int cs = atomicAdd(&d_ccnt[j], 1);
                        if (cs < CAP) d_clist[j * CAP + cs] = row;
                    }
                }
            }
        }
        __syncthreads();
        int n = min(s_cnt, CAP);
        if (tid == 0) d_rcnt[row] = n;
        for (int i = tid; i < n; i += 256) d_rlist[row * CAP + i] = s_list[i];
        __syncthreads();
    }
    gbar(nb, gen);

    // ---- P2: layer 1 (8,8)->(8,8) ----
    for (int i = tid; i < 128; i += 256) { sWp[i] = wp1[i]; sWt[i] = wt1[i]; }
    if (tid < 8) { sBp[tid] = bp1[tid]; sBt[tid] = bt1[tid]; }
    __syncthreads();
    for (int idx = gw; idx < NP + NT; idx += tw) {
        if (idx < NP) layer_node<8, 8, true >(idx,      p0, t0, d_rcnt, d_rlist, sWp, sBp, d_pa, sX[warp], lane);
        else          layer_node<8, 8, false>(idx - NP, t0, p0, d_ccnt, d_clist, sWt, sBt, d_ta, sX[warp], lane);
    }
    gbar(nb, gen);

    // ---- P3: layer 2 (8,8)->(16,16) ----
    for (int i = tid; i < 256; i += 256) { sWp[i] = wp2[i]; sWt[i] = wt2[i]; }
    if (tid < 16) { sBp[tid] = bp2[tid]; sBt[tid] = bt2[tid]; }
    __syncthreads();
    for (int idx = gw; idx < NP + NT; idx += tw) {
        if (idx < NP) layer_node<8, 16, true >(idx,      d_pa, d_ta, d_rcnt, d_rlist, sWp, sBp, d_pb, sX[warp], lane);
        else          layer_node<8, 16, false>(idx - NP, d_ta, d_pa, d_ccnt, d_clist, sWt, sBt, d_tb, sX[warp], lane);
    }
    gbar(nb, gen);

    // ---- P4: layer 3 (16,16)->(64,64) ----
    for (int i = tid; i < 2048; i += 256) { sWp[i] = wp3[i]; sWt[i] = wt3[i]; }
    if (tid < 64) { sBp[tid] = bp3[tid]; sBt[tid] = bt3[tid]; }
    __syncthreads();
    for (int idx = gw; idx < NP + NT; idx += tw) {
        if (idx < NP) layer_node<16, 64, true >(idx,      d_pb, d_tb, d_rcnt, d_rlist, sWp, sBp, d_pa, sX[warp], lane);
        else          layer_node<16, 64, false>(idx - NP, d_tb, d_pb, d_ccnt, d_clist, sWt, sBt, d_ta, sX[warp], lane);
    }
    gbar(nb, gen);

    // ---- P5: layer 4 projection: proj = feat64 @ Wagg (-> 16) ----
    // p side concat = [p_self(64) | agg_t(64)]: Wp rows [0,64)=self, [64,128)=agg
    // t side concat = [agg_p(64) | t_self(64)]: Wt rows [0,64)=agg, [64,128)=self
    for (int i = tid; i < 2048; i += 256) { sWp[i] = wp4[i]; sWt[i] = wt4[i]; }
    if (tid < 16) { sBp[tid] = bp4[tid]; sBt[tid] = bt4[tid]; }
    if (tid < 32) sAC[tid] = wac[tid];
    __syncthreads();
    for (int idx = gw; idx < NP + NT; idx += tw) {
        if (idx < NP) proj_node<64, 16>(idx,      d_pa, sWt,        d_prt, sX[warp], lane);  // p feats @ Wt_agg
        else          proj_node<64, 16>(idx - NP, d_ta, sWp + 1024, d_prp, sX[warp], lane);  // t feats @ Wp_agg
    }
    gbar(nb, gen);

    // ---- P6: layer 4 combine + per-node w_ac dot (weights still in smem) ----
    for (int idx = gw; idx < NP + NT; idx += tw) {
        if (idx < NP) l4_node<64, 16>(idx,      d_pa, d_prp, d_rcnt, d_rlist, sWp,        sBp, sAC,      d_pb, d_lp, sX[warp], lane);
        else          l4_node<64, 16>(idx - NP, d_ta, d_prt, d_ccnt, d_clist, sWt + 1024, sBt, sAC + 16, d_tb, d_td, sX[warp], lane);
    }
    gbar(nb, gen);

    // ---- P7: logits: gather scalar lp over columns + t-side dot + bias ----
    {
        float bias = bac[0];
        for (int idx = gw; idx < NT; idx += tw) {
            int n = min(d_ccnt[idx], CAP);
            const int* lst = d_clist + idx * CAP;
            float s = 0.f;
            for (int e = lane; e < n; e += 32) s += d_lp[lst[e]];
#pragma unroll
            for (int d = 16; d > 0; d >>= 1) s += __shfl_down_sync(0xffffffffu, s, d);
            if (lane == 0) d_logits[idx] = s + d_td[idx] + bias;
        }
    }
    gbar(nb, gen);

    // ---- P8: softmax reduce (block 0) ----
    if (blockIdx.x == 0) {
        float m = -1e30f;
        for (int i = tid; i < NT; i += 256) m = fmaxf(m, d_logits[i]);
        sRed[tid] = m; __syncthreads();
        for (int s = 128; s > 0; s >>= 1) {
            if (tid < s) sRed[tid] = fmaxf(sRed[tid], sRed[tid + s]);
            __syncthreads();
        }
        float mx = sRed[0]; __syncthreads();
        float sum = 0.f;
        for (int i = tid; i < NT; i += 256) sum += __expf(d_logits[i] - mx);
        sRed[tid] = sum; __syncthreads();
        for (int s = 128; s > 0; s >>= 1) {
            if (tid < s) sRed[tid] += sRed[tid + s];
            __syncthreads();
        }
        if (tid == 0) { g_max = mx; g_inv = 1.f / sRed[0]; }
    }
    gbar(nb, gen);

    // ---- P9: write softmax output ----
    {
        float mx = g_max, inv = g_inv;
        for (int i = blockIdx.x * 256 + tid; i < NT; i += nb * 256)
            out[i] = __expf(d_logits[i] - mx) * inv;
    }
}

// ---------------- launch ----------------
extern "C" void kernel_launch(void* const* d_in, const int* in_sizes, int n_in,
                              void* d_out, int out_size) {
    const float* p    = (const float*)d_in[0];
    const float* t    = (const float*)d_in[1];
    const float* adj  = (const float*)d_in[2];
    const float* w_p1 = (const float*)d_in[3];  const float* b_p1 = (const float*)d_in[4];
    const float* w_t1 = (const float*)d_in[5];  const float* b_t1 = (const float*)d_in[6];
    const float* w_p2 = (const float*)d_in[7];  const float* b_p2 = (const float*)d_in[8];
    const float* w_t2 = (const float*)d_in[9];  const float* b_t2 = (const float*)d_in[10];
    const float* w_p3 = (const float*)d_in[11]; const float* b_p3 = (const float*)d_in[12];
    const float* w_t3 = (const float*)d_in[13]; const float* b_t3 = (const float*)d_in[14];
    const float* w_p4 = (const float*)d_in[15]; const float* b_p4 = (const float*)d_in[16];
    const float* w_t4 = (const float*)d_in[17]; const float* b_t4 = (const float*)d_in[18];
    const float* w_ac = (const float*)d_in[19]; const float* b_ac = (const float*)d_in[20];
    float* out = (float*)d_out;

    int dev = 0;
    cudaGetDevice(&dev);
    int sms = 0;
    cudaDeviceGetAttribute(&sms, cudaDevAttrMultiProcessorCount, dev);
    int bpm = 0;
    cudaOccupancyMaxActiveBlocksPerMultiprocessor(&bpm, fused_k, 256, 0);
    if (bpm < 1) bpm = 1;
    int nb = sms * bpm;
    if (nb > NP) nb = NP;

    fused_k<<<nb, 256>>>(p, t, adj,
                         w_p1, b_p1, w_t1, b_t1,
                         w_p2, b_p2, w_t2, b_t2,
                         w_p3, b_p3, w_t3, b_t3,
                         w_p4, b_p4, w_t4, b_t4,
                         w_ac, b_ac, out, nb);
}